// round 15
// baseline (speedup 1.0000x reference)
#include <cuda_runtime.h>
#include <cstdint>
#include <math.h>

#define BATCH 2
#define TLEN  1024
#define NH    8
#define HDIM  64
#define HID   512
#define KDIM  512
#define BT    (BATCH*TLEN)
#define PADROWS 8

// ---------------- scratch (q/k/v + gating padded for unconditional prefetch) --
__device__ float g_xq[BT*KDIM];
__device__ float g_xk[BT*KDIM];
__device__ float g_xv[BT*KDIM];
__device__ float g_q [BT*KDIM + PADROWS*KDIM];
__device__ float g_k [BT*KDIM + PADROWS*KDIM];
__device__ float g_v [BT*KDIM + PADROWS*KDIM];
__device__ float g_g [BT*KDIM];
__device__ float g_oc[BT*KDIM];
__device__ float g_act[BT*KDIM];
__device__ float g_p0[BT*KDIM];
__device__ float g_p1[BT*KDIM];
__device__ float g_beta [BT*NH + PADROWS*NH];
__device__ float g_alpha[BT*NH + PADROWS*NH];
__device__ float g_c1   [BT*NH + PADROWS*NH];
__device__ float g_c2   [BT*NH + PADROWS*NH];
__device__ float g_cos[TLEN*32];
__device__ float g_sin[TLEN*32];

// ---------------- helpers ----------------
__device__ __forceinline__ float red32(float x)
{
#pragma unroll
    for (int m = 16; m; m >>= 1) x += __shfl_xor_sync(0xffffffffu, x, m);
    return x;
}

// ---------------- GEMM 128x128 body, parametric K range -----------------------
__device__ __forceinline__ void gemm128_body(const float* __restrict__ A,
                                             const float* __restrict__ Bw,
                                             float* __restrict__ C,
                                             int kbase, int KT)
{
    __shared__ __align__(16) float As[2][16][132];
    __shared__ __align__(16) float Bs[2][16][132];
    const int tid = threadIdx.x;
    const int tx = tid & 15, ty = tid >> 4;
    const int m0 = blockIdx.y * 128, n0 = blockIdx.x * 128;

    const int r0 = (tid)       >> 2, q0 = ((tid)       & 3) << 2;
    const int r1 = (tid + 256) >> 2, q1 = ((tid + 256) & 3) << 2;

    const float* aptr0 = A  + (size_t)(m0 + r0) * 512 + kbase + q0;
    const float* aptr1 = A  + (size_t)(m0 + r1) * 512 + kbase + q1;
    const float* bptr0 = Bw + (size_t)(n0 + r0) * 512 + kbase + q0;
    const float* bptr1 = Bw + (size_t)(n0 + r1) * 512 + kbase + q1;

    float acc[8][8];
#pragma unroll
    for (int i = 0; i < 8; i++)
#pragma unroll
        for (int j = 0; j < 8; j++) acc[i][j] = 0.0f;

    float4 va0 = *(const float4*)(aptr0);
    float4 va1 = *(const float4*)(aptr1);
    float4 vb0 = *(const float4*)(bptr0);
    float4 vb1 = *(const float4*)(bptr1);
    {
        As[0][q0 + 0][r0] = va0.x; As[0][q0 + 1][r0] = va0.y;
        As[0][q0 + 2][r0] = va0.z; As[0][q0 + 3][r0] = va0.w;
        As[0][q1 + 0][r1] = va1.x; As[0][q1 + 1][r1] = va1.y;
        As[0][q1 + 2][r1] = va1.z; As[0][q1 + 3][r1] = va1.w;
        Bs[0][q0 + 0][r0] = vb0.x; Bs[0][q0 + 1][r0] = vb0.y;
        Bs[0][q0 + 2][r0] = vb0.z; Bs[0][q0 + 3][r0] = vb0.w;
        Bs[0][q1 + 0][r1] = vb1.x; Bs[0][q1 + 1][r1] = vb1.y;
        Bs[0][q1 + 2][r1] = vb1.z; Bs[0][q1 + 3][r1] = vb1.w;
    }
    __syncthreads();

    for (int kt = 0; kt < KT; kt++) {
        const int cur = kt & 1;
        if (kt + 1 < KT) {
            int ko = (kt + 1) * 16;
            va0 = *(const float4*)(aptr0 + ko);
            va1 = *(const float4*)(aptr1 + ko);
            vb0 = *(const float4*)(bptr0 + ko);
            vb1 = *(const float4*)(bptr1 + ko);
        }
#pragma unroll
        for (int kk = 0; kk < 16; kk++) {
            float4 a0 = *(const float4*)&As[cur][kk][ty * 8];
            float4 a1 = *(const float4*)&As[cur][kk][ty * 8 + 4];
            float4 b0 = *(const float4*)&Bs[cur][kk][tx * 8];
            float4 b1 = *(const float4*)&Bs[cur][kk][tx * 8 + 4];
            float av[8] = {a0.x, a0.y, a0.z, a0.w, a1.x, a1.y, a1.z, a1.w};
            float bv[8] = {b0.x, b0.y, b0.z, b0.w, b1.x, b1.y, b1.z, b1.w};
#pragma unroll
            for (int i = 0; i < 8; i++)
#pragma unroll
                for (int j = 0; j < 8; j++)
                    acc[i][j] = fmaf(av[i], bv[j], acc[i][j]);
        }
        if (kt + 1 < KT) {
            const int nxt = cur ^ 1;
            As[nxt][q0 + 0][r0] = va0.x; As[nxt][q0 + 1][r0] = va0.y;
            As[nxt][q0 + 2][r0] = va0.z; As[nxt][q0 + 3][r0] = va0.w;
            As[nxt][q1 + 0][r1] = va1.x; As[nxt][q1 + 1][r1] = va1.y;
            As[nxt][q1 + 2][r1] = va1.z; As[nxt][q1 + 3][r1] = va1.w;
            Bs[nxt][q0 + 0][r0] = vb0.x; Bs[nxt][q0 + 1][r0] = vb0.y;
            Bs[nxt][q0 + 2][r0] = vb0.z; Bs[nxt][q0 + 3][r0] = vb0.w;
            Bs[nxt][q1 + 0][r1] = vb1.x; Bs[nxt][q1 + 1][r1] = vb1.y;
            Bs[nxt][q1 + 2][r1] = vb1.z; Bs[nxt][q1 + 3][r1] = vb1.w;
            __syncthreads();
        }
    }
#pragma unroll
    for (int i = 0; i < 8; i++) {
        float* crow = C + (size_t)(m0 + ty * 8 + i) * 512 + n0 + tx * 8;
        *(float4*)(crow)     = make_float4(acc[i][0], acc[i][1], acc[i][2], acc[i][3]);
        *(float4*)(crow + 4) = make_float4(acc[i][4], acc[i][5], acc[i][6], acc[i][7]);
    }
}

__global__ __launch_bounds__(256, 2) void gemm128_qkvg(const float* __restrict__ x,
    const float* __restrict__ Wq, const float* __restrict__ Wk,
    const float* __restrict__ Wv, const float* __restrict__ Wg)
{
    const float* Bw; float* C;
    switch (blockIdx.z) {
        case 0:  Bw = Wq; C = g_xq; break;
        case 1:  Bw = Wk; C = g_xk; break;
        case 2:  Bw = Wv; C = g_xv; break;
        default: Bw = Wg; C = g_g;  break;
    }
    gemm128_body(x, Bw, C, 0, 32);
}

// output projection: split-K x2 into partial buffers
__global__ __launch_bounds__(256, 2) void gemm_out_k(const float* __restrict__ Wo)
{
    float* C = blockIdx.z ? g_p1 : g_p0;
    gemm128_body(g_act, Wo, C, blockIdx.z * 256, 16);
}

__global__ __launch_bounds__(256) void add_out(float* __restrict__ out)
{
    int i = blockIdx.x * blockDim.x + threadIdx.x;
    if (i >= BT * KDIM / 4) return;
    float4 a = *(const float4*)(g_p0 + (size_t)i * 4);
    float4 b = *(const float4*)(g_p1 + (size_t)i * 4);
    *(float4*)(out + (size_t)i * 4) =
        make_float4(a.x + b.x, a.y + b.y, a.z + b.z, a.w + b.w);
}

// ---------------- beta/alpha small projection + rope tables (merged) ----------
// Blocks 0..BT-1: projection for row bt. Blocks BT..BT+127: rope table init.
__global__ __launch_bounds__(128) void small_proj(const float* __restrict__ x,
    const float* __restrict__ Wb, const float* __restrict__ bb,
    const float* __restrict__ Wgk, const float* __restrict__ bgk,
    const float* __restrict__ A_log, const float* __restrict__ dtb)
{
    if (blockIdx.x >= BT) {
        // rope init partition: 128 blocks x 128 threads cover 16384 entries x2
        int idx = (blockIdx.x - BT) * 128 + threadIdx.x;
        for (int pass = 0; pass < 2; pass++) {
            int id = idx + pass * 16384;
            if (id < TLEN * 32) {
                int t = id >> 5, j = id & 31;
                const double PI = 3.14159265358979323846;
                double ar = (double)j / 32.0;
                double sbase = 10000.0 * pow(32.0, 64.0 / 62.0);
                double inv_freq = pow(sbase, -ar);
                double freq_extra = pow(10000.0, -ar);
                double wavelen = (2.0 * PI) / freq_extra;
                double ramp = (wavelen - 1.0) / 31.0;
                ramp = ramp < 0.0 ? 0.0 : (ramp > 1.0 ? 1.0 : ramp);
                double spf = 1.0 + 31.0 * ramp;
                double f = (double)t / spf * inv_freq;
                g_cos[id] = (float)cos(f);
                g_sin[id] = (float)sin(f);
            }
        }
        return;
    }
    __shared__ float xs[512];
    const int bt = blockIdx.x;
    const int tid = threadIdx.x;
    for (int i = tid; i < 512; i += 128) xs[i] = x[(size_t)bt * 512 + i];
    __syncthreads();
    const int warp = tid >> 5, lane = tid & 31;
#pragma unroll
    for (int oi = 0; oi < 4; oi++) {
        int out = warp * 4 + oi;
        const float* w = (out < 8) ? (Wb + out * 512) : (Wgk + (out - 8) * 512);
        float s = 0.0f;
#pragma unroll
        for (int i = 0; i < 16; i++) s = fmaf(xs[lane + i * 32], w[lane + i * 32], s);
        s = red32(s);
        if (lane == 0) {
            if (out < 8) {
                float z = s + bb[out];
                g_beta[bt * 8 + out] = 1.0f / (1.0f + expf(-z));
            } else {
                int h = out - 8;
                float z = s + bgk[h] + dtb[h];
                float sp = (z > 20.0f) ? z : log1pf(expf(z));
                g_alpha[bt * 8 + h] = expf(-expf(A_log[h]) * sp);
            }
        }
    }
}

// ---------------- depthwise causal conv (width 4) + silu ----------------------
__global__ __launch_bounds__(128) void conv_silu(
    const float* __restrict__ cqw, const float* __restrict__ cqb,
    const float* __restrict__ ckw, const float* __restrict__ ckb,
    const float* __restrict__ cvw, const float* __restrict__ cvb)
{
    const float *xin, *w, *bi; float* out;
    switch (blockIdx.y) {
        case 0:  xin = g_xq; w = cqw; bi = cqb; out = g_q; break;
        case 1:  xin = g_xk; w = ckw; bi = ckb; out = g_k; break;
        default: xin = g_xv; w = cvw; bi = cvb; out = g_v; break;
    }
    const int c = threadIdx.x * 4;
    const int t0 = blockIdx.x * 8;
    const int b  = blockIdx.z;

    float4 wr0 = *(const float4*)(w + (c + 0) * 4);
    float4 wr1 = *(const float4*)(w + (c + 1) * 4);
    float4 wr2 = *(const float4*)(w + (c + 2) * 4);
    float4 wr3 = *(const float4*)(w + (c + 3) * 4);
    float4 bias = *(const float4*)(bi + c);

    const float* xrow = xin + (size_t)b * TLEN * 512 + c;
    float*       orow = out + (size_t)b * TLEN * 512 + c;
    const float4 zero = make_float4(0.f, 0.f, 0.f, 0.f);

    float4 h0 = (t0 - 3 >= 0) ? *(const float4*)(xrow + (size_t)(t0 - 3) * 512) : zero;
    float4 h1 = (t0 - 2 >= 0) ? *(const float4*)(xrow + (size_t)(t0 - 2) * 512) : zero;
    float4 h2 = (t0 - 1 >= 0) ? *(const float4*)(xrow + (size_t)(t0 - 1) * 512) : zero;
    float4 cur = *(const float4*)(xrow + (size_t)t0 * 512);

#pragma unroll
    for (int t = t0; t < t0 + 8; t++) {
        float4 nxt = (t + 1 < TLEN) ? *(const float4*)(xrow + (size_t)(t + 1) * 512) : zero;
        float4 acc = bias;
        acc.x = fmaf(h0.x, wr0.x, acc.x); acc.x = fmaf(h1.x, wr0.y, acc.x);
        acc.x = fmaf(h2.x, wr0.z, acc.x); acc.x = fmaf(cur.x, wr0.w, acc.x);
        acc.y = fmaf(h0.y, wr1.x, acc.y); acc.y = fmaf(h1.y, wr1.y, acc.y);
        acc.y = fmaf(h2.y, wr1.z, acc.y); acc.y = fmaf(cur.y, wr1.w, acc.y);
        acc.z = fmaf(h0.z, wr2.x, acc.z); acc.z = fmaf(h1.z, wr2.y, acc.z);
        acc.z = fmaf(h2.z, wr2.z, acc.z); acc.z = fmaf(cur.z, wr2.w, acc.z);
        acc.w = fmaf(h0.w, wr3.x, acc.w); acc.w = fmaf(h1.w, wr3.y, acc.w);
        acc.w = fmaf(h2.w, wr3.z, acc.w); acc.w = fmaf(cur.w, wr3.w, acc.w);
        float4 o;
        o.x = acc.x / (1.0f + expf(-acc.x));
        o.y = acc.y / (1.0f + expf(-acc.y));
        o.z = acc.z / (1.0f + expf(-acc.z));
        o.w = acc.w / (1.0f + expf(-acc.w));
        *(float4*)(orow + (size_t)t * 512) = o;
        h0 = h1; h1 = h2; h2 = cur; cur = nxt;
    }
}

// ---------------- RoPE + l2norm, in-place on g_q / g_k ------------------------
__global__ __launch_bounds__(256) void rope_l2norm()
{
    int gw = (blockIdx.x * blockDim.x + threadIdx.x) >> 5;
    int lane = threadIdx.x & 31;
    if (gw >= BT * NH) return;
    int t = (gw >> 3) & 1023;
    int j = (2 * lane) & 31;
    float c = g_cos[t * 32 + j], s = g_sin[t * 32 + j];
    size_t base = (size_t)gw * 64;
#pragma unroll
    for (int which = 0; which < 2; which++) {
        float* p = which ? g_k : g_q;
        float x1 = p[base + 2 * lane];
        float x2 = p[base + 2 * lane + 1];
        float o1 = x1 * c - x2 * s;
        float o2 = x1 * s + x2 * c;
        float ss = red32(o1 * o1 + o2 * o2);
        float inv = 1.0f / fmaxf(sqrtf(ss), 1e-12f);
        p[base + lane]      = o1 * inv;
        p[base + 32 + lane] = o2 * inv;
    }
}

// ---------------- c1[t]=k_t.k_{t-1}, c2[t]=k_t.k_{t-2} precompute -------------
__global__ __launch_bounds__(256) void c12_prep()
{
    int gw = (blockIdx.x * (blockDim.x >> 5)) + (threadIdx.x >> 5);
    int lane = threadIdx.x & 31;
    if (gw >= BT * NH) return;
    int h = gw & 7, bt = gw >> 3;
    int t = bt & 1023;
    const float* ka = g_k + (size_t)bt * 512 + h * 64;
    float2 xx = *(const float2*)(ka + lane * 2);
    float cv1 = 0.0f, cv2 = 0.0f;
    if (t > 0) {
        float2 yy = *(const float2*)(ka - 512 + lane * 2);
        cv1 = red32(fmaf(xx.x, yy.x, xx.y * yy.y));
    }
    if (t > 1) {
        float2 zz = *(const float2*)(ka - 1024 + lane * 2);
        cv2 = red32(fmaf(xx.x, zz.x, xx.y * zz.y));
    }
    if (lane == 0) {
        g_c1[(size_t)bt * 8 + h] = cv1;
        g_c2[(size_t)bt * 8 + h] = cv2;
    }
}

// ---------------- delta-rule scan (look-ahead-3, pipelined reductions) --------
// u_t = a_{t-1}a_{t-2} r_t + a_{t-1} w_{t-2} c2_t + w_{t-1} c1_t,
//   r_t = k_t^T S_{t-3}; w_t = b_t(v_t - a_t u_t); S_t = a_t S_{t-1} + w_t k_t.
__global__ __launch_bounds__(128) void scan_kernel()
{
    const int bh = blockIdx.x;
    const int eg = blockIdx.y;
    const int b = bh >> 3, h = bh & 7;
    const int w = threadIdx.x >> 5, lane = threadIdx.x & 31;
    const int el = lane >> 4, r = lane & 15;
    const int e  = eg * 8 + w * 2 + el;
    const int d0 = r * 4;

    const size_t head = ((size_t)b * TLEN * NH + h) * 64;
    const float* qp  = g_q + head + d0;
    const float* kp  = g_k + head + d0;
    const float* vpt = g_v + head + e;
    float*       op  = g_oc + head + e;
    const float* apt = g_alpha + (size_t)b * TLEN * NH + h;
    const float* bpt = g_beta  + (size_t)b * TLEN * NH + h;
    const float* cpt = g_c1    + (size_t)b * TLEN * NH + h;
    const float* c2pt= g_c2    + (size_t)b * TLEN * NH + h;

    float4 S = make_float4(0.f, 0.f, 0.f, 0.f);
    float w_prev1 = 0.f, w_prev2 = 0.f, a_prev1 = 0.f, a_prev2 = 0.f;
    float h1 = 0.f, oh1 = 0.f, r_use = 0.f, r_hold = 0.f;

    float4 kb[8];
    float4 qb[4];
    float  vb[4], ab[4], bb2[4], cb[4], c2b[4];
#pragma unroll
    for (int i = 0; i < 6; i++) kb[i] = *(const float4*)(kp + (size_t)i * 512);
    kb[6] = kb[7] = make_float4(0.f, 0.f, 0.f, 0.f);
#pragma unroll
    for (int i = 0; i < 4; i++) {
        qb[i]  = *(const float4*)(qp + (size_t)i * 512);
        vb[i]  = vpt[(size_t)i * 512];
        ab[i]  = apt[(size_t)i * 8];
        bb2[i] = bpt[(size_t)i * 8];
        cb[i]  = cpt[(size_t)i * 8];
        c2b[i] = c2pt[(size_t)i * 8];
    }

#pragma unroll 8
    for (int t = 0; t < TLEN; t++) {
        const float4 kc  = kb[t & 7];
        const float4 kf  = kb[(t + 3) & 7];   // k_{t+3} for r partial
        const float4 qc  = qb[t & 3];
        const float  vc  = vb[t & 3];
        const float  ac  = ab[t & 3];
        const float  bc  = bb2[t & 3];
        const float  c1c = cb[t & 3];
        const float  c2c = c2b[t & 3];

        float u = fmaf(a_prev1 * a_prev2, r_use,
                       fmaf(a_prev1 * w_prev2, c2c, w_prev1 * c1c));
        float wv = bc * fmaf(-ac, u, vc);
        S.x = fmaf(kc.x, wv, ac * S.x);
        S.y = fmaf(kc.y, wv, ac * S.y);
        S.z = fmaf(kc.z, wv, ac * S.z);
        S.w = fmaf(kc.w, wv, ac * S.w);

        float h2 = h1 + __shfl_xor_sync(0xffffffffu, h1, 2);
        float rnew = h2 + __shfl_xor_sync(0xffffffffu, h2, 1);
        float og = oh1 + __shfl_xor_sync(0xffffffffu, oh1, 2);
        float o_fin = og + __shfl_xor_sync(0xffffffffu, og, 1);
        if (r == 0 && t > 0) op[-512] = o_fin;

        float rp = fmaf(kf.x, S.x, fmaf(kf.y, S.y, fmaf(kf.z, S.z, kf.w * S.w)));
        float rh = rp + __shfl_xor_sync(0xffffffffu, rp, 8);
        h1 = rh + __shfl_xor_sync(0xffffffffu, rh, 4);
        float opp = fmaf(qc.x, S.x, fmaf(qc.y, S.y, fmaf(qc.z, S.z, qc.w * S.w)));
        float oh = opp + __shfl_xor_sync(0xffffffffu, opp, 8);
        oh1 = oh + __shfl_xor_sync(0xffffffffu, oh, 4);

        r_use = r_hold; r_hold = rnew;
        w_prev2 = w_prev1; w_prev1 = wv;
        a_prev2 = a_prev1; a_prev1 = ac;

        kb[(t + 6) & 7] = *(const float4*)(kp + 6 * 512);
        qb[(t + 4) & 3] = *(const float4*)(qp + 4 * 512);
        vb[(t + 4) & 3]  = vpt[4 * 512];
        ab[(t + 4) & 3]  = apt[4 * 8];
        bb2[(t + 4) & 3] = bpt[4 * 8];
        cb[(t + 4) & 3]  = cpt[4 * 8];
        c2b[(t + 4) & 3] = c2pt[4 * 8];
        kp += 512; qp += 512; vpt += 512; op += 512;
        apt += 8; bpt += 8; cpt += 8; c2pt += 8;
    }
    float og = oh1 + __shfl_xor_sync(0xffffffffu, oh1, 2);
    float o_fin = og + __shfl_xor_sync(0xffffffffu, og, 1);
    if (r == 0) op[-512] = o_fin;
}

// ---------------- post: +D*v, RMS norm, gate ----------------------------------
__global__ __launch_bounds__(256) void postproc(const float* __restrict__ D,
                                                const float* __restrict__ onw)
{
    int gw = (blockIdx.x * blockDim.x + threadIdx.x) >> 5;
    int lane = threadIdx.x & 31;
    if (gw >= BT * NH) return;
    int h = gw & 7;
    size_t base = (size_t)gw * 64;
    float d = D[h];
    float o1 = g_oc[base + lane]      + d * g_v[base + lane];
    float o2 = g_oc[base + 32 + lane] + d * g_v[base + 32 + lane];
    float ss = red32(o1 * o1 + o2 * o2);
    float sc = rsqrtf(ss * (1.0f / 64.0f) + 1e-6f);
    float on1 = o1 * sc * onw[lane];
    float on2 = o2 * sc * onw[32 + lane];
    float g1 = g_g[base + lane], g2 = g_g[base + 32 + lane];
    g_act[base + lane]      = g1 * (on1 / (1.0f + expf(-on1)));
    g_act[base + 32 + lane] = g2 * (on2 / (1.0f + expf(-on2)));
}

// ---------------- launch ------------------------------------------------------
extern "C" void kernel_launch(void* const* d_in, const int* in_sizes, int n_in,
                              void* d_out, int out_size)
{
    const float* x    = (const float*)d_in[0];
    const float* Wq   = (const float*)d_in[1];
    const float* Wk   = (const float*)d_in[2];
    const float* Wv   = (const float*)d_in[3];
    const float* Wg   = (const float*)d_in[4];
    const float* Wo   = (const float*)d_in[5];
    const float* Wb   = (const float*)d_in[6];
    const float* bb   = (const float*)d_in[7];
    const float* Wgk  = (const float*)d_in[8];
    const float* bgk  = (const float*)d_in[9];
    const float* cqw  = (const float*)d_in[10];
    const float* cqb  = (const float*)d_in[11];
    const float* ckw  = (const float*)d_in[12];
    const float* ckb  = (const float*)d_in[13];
    const float* cvw  = (const float*)d_in[14];
    const float* cvb  = (const float*)d_in[15];
    const float* A_log= (const float*)d_in[16];
    const float* D    = (const float*)d_in[17];
    const float* dtb  = (const float*)d_in[18];
    const float* onw  = (const float*)d_in[19];
    float* out = (float*)d_out;

    gemm128_qkvg<<<dim3(4, 16, 4), 256>>>(x, Wq, Wk, Wv, Wg);
    small_proj<<<BT + 128, 128>>>(x, Wb, bb, Wgk, bgk, A_log, dtb);
    conv_silu<<<dim3(TLEN / 8, 3, 2), 128>>>(cqw, cqb, ckw, ckb, cvw, cvb);
    rope_l2norm<<<2048, 256>>>();
    c12_prep<<<(BT * NH + 7) / 8, 256>>>();
    scan_kernel<<<dim3(16, 8), 128>>>();
    postproc<<<2048, 256>>>(D, onw);
    gemm_out_k<<<dim3(4, 16, 2), 256>>>(Wo);
    add_out<<<(BT * KDIM / 4 + 255) / 256, 256>>>(out);
}

// round 16
// speedup vs baseline: 1.2778x; 1.2778x over previous
#include <cuda_runtime.h>
#include <cstdint>
#include <math.h>

#define BATCH 2
#define TLEN  1024
#define NH    8
#define HDIM  64
#define HID   512
#define KDIM  512
#define BT    (BATCH*TLEN)
#define PADROWS 8

// ---------------- scratch (q/k/v + gating padded for unconditional prefetch) --
__device__ float g_xq[BT*KDIM];
__device__ float g_xk[BT*KDIM];
__device__ float g_xv[BT*KDIM];
__device__ float g_q [BT*KDIM + PADROWS*KDIM];
__device__ float g_k [BT*KDIM + PADROWS*KDIM];
__device__ float g_v [BT*KDIM + PADROWS*KDIM];
__device__ float g_g [BT*KDIM];
__device__ float g_oc[BT*KDIM];
__device__ float g_act[BT*KDIM];
__device__ float g_p0[BT*KDIM];
__device__ float g_p1[BT*KDIM];
__device__ float g_beta [BT*NH + PADROWS*NH];
__device__ float g_alpha[BT*NH + PADROWS*NH];
__device__ float g_c1   [BT*NH + PADROWS*NH];
__device__ float g_c2   [BT*NH + PADROWS*NH];
__device__ float g_cos[TLEN*32];
__device__ float g_sin[TLEN*32];

// ---------------- helpers ----------------
__device__ __forceinline__ float red32(float x)
{
#pragma unroll
    for (int m = 16; m; m >>= 1) x += __shfl_xor_sync(0xffffffffu, x, m);
    return x;
}

// ---------------- GEMM 128x128 body, parametric K range -----------------------
__device__ __forceinline__ void gemm128_body(const float* __restrict__ A,
                                             const float* __restrict__ Bw,
                                             float* __restrict__ C,
                                             int kbase, int KT)
{
    __shared__ __align__(16) float As[2][16][132];
    __shared__ __align__(16) float Bs[2][16][132];
    const int tid = threadIdx.x;
    const int tx = tid & 15, ty = tid >> 4;
    const int m0 = blockIdx.y * 128, n0 = blockIdx.x * 128;

    const int r0 = (tid)       >> 2, q0 = ((tid)       & 3) << 2;
    const int r1 = (tid + 256) >> 2, q1 = ((tid + 256) & 3) << 2;

    const float* aptr0 = A  + (size_t)(m0 + r0) * 512 + kbase + q0;
    const float* aptr1 = A  + (size_t)(m0 + r1) * 512 + kbase + q1;
    const float* bptr0 = Bw + (size_t)(n0 + r0) * 512 + kbase + q0;
    const float* bptr1 = Bw + (size_t)(n0 + r1) * 512 + kbase + q1;

    float acc[8][8];
#pragma unroll
    for (int i = 0; i < 8; i++)
#pragma unroll
        for (int j = 0; j < 8; j++) acc[i][j] = 0.0f;

    float4 va0 = *(const float4*)(aptr0);
    float4 va1 = *(const float4*)(aptr1);
    float4 vb0 = *(const float4*)(bptr0);
    float4 vb1 = *(const float4*)(bptr1);
    {
        As[0][q0 + 0][r0] = va0.x; As[0][q0 + 1][r0] = va0.y;
        As[0][q0 + 2][r0] = va0.z; As[0][q0 + 3][r0] = va0.w;
        As[0][q1 + 0][r1] = va1.x; As[0][q1 + 1][r1] = va1.y;
        As[0][q1 + 2][r1] = va1.z; As[0][q1 + 3][r1] = va1.w;
        Bs[0][q0 + 0][r0] = vb0.x; Bs[0][q0 + 1][r0] = vb0.y;
        Bs[0][q0 + 2][r0] = vb0.z; Bs[0][q0 + 3][r0] = vb0.w;
        Bs[0][q1 + 0][r1] = vb1.x; Bs[0][q1 + 1][r1] = vb1.y;
        Bs[0][q1 + 2][r1] = vb1.z; Bs[0][q1 + 3][r1] = vb1.w;
    }
    __syncthreads();

    for (int kt = 0; kt < KT; kt++) {
        const int cur = kt & 1;
        if (kt + 1 < KT) {
            int ko = (kt + 1) * 16;
            va0 = *(const float4*)(aptr0 + ko);
            va1 = *(const float4*)(aptr1 + ko);
            vb0 = *(const float4*)(bptr0 + ko);
            vb1 = *(const float4*)(bptr1 + ko);
        }
#pragma unroll
        for (int kk = 0; kk < 16; kk++) {
            float4 a0 = *(const float4*)&As[cur][kk][ty * 8];
            float4 a1 = *(const float4*)&As[cur][kk][ty * 8 + 4];
            float4 b0 = *(const float4*)&Bs[cur][kk][tx * 8];
            float4 b1 = *(const float4*)&Bs[cur][kk][tx * 8 + 4];
            float av[8] = {a0.x, a0.y, a0.z, a0.w, a1.x, a1.y, a1.z, a1.w};
            float bv[8] = {b0.x, b0.y, b0.z, b0.w, b1.x, b1.y, b1.z, b1.w};
#pragma unroll
            for (int i = 0; i < 8; i++)
#pragma unroll
                for (int j = 0; j < 8; j++)
                    acc[i][j] = fmaf(av[i], bv[j], acc[i][j]);
        }
        if (kt + 1 < KT) {
            const int nxt = cur ^ 1;
            As[nxt][q0 + 0][r0] = va0.x; As[nxt][q0 + 1][r0] = va0.y;
            As[nxt][q0 + 2][r0] = va0.z; As[nxt][q0 + 3][r0] = va0.w;
            As[nxt][q1 + 0][r1] = va1.x; As[nxt][q1 + 1][r1] = va1.y;
            As[nxt][q1 + 2][r1] = va1.z; As[nxt][q1 + 3][r1] = va1.w;
            Bs[nxt][q0 + 0][r0] = vb0.x; Bs[nxt][q0 + 1][r0] = vb0.y;
            Bs[nxt][q0 + 2][r0] = vb0.z; Bs[nxt][q0 + 3][r0] = vb0.w;
            Bs[nxt][q1 + 0][r1] = vb1.x; Bs[nxt][q1 + 1][r1] = vb1.y;
            Bs[nxt][q1 + 2][r1] = vb1.z; Bs[nxt][q1 + 3][r1] = vb1.w;
            __syncthreads();
        }
    }
#pragma unroll
    for (int i = 0; i < 8; i++) {
        float* crow = C + (size_t)(m0 + ty * 8 + i) * 512 + n0 + tx * 8;
        *(float4*)(crow)     = make_float4(acc[i][0], acc[i][1], acc[i][2], acc[i][3]);
        *(float4*)(crow + 4) = make_float4(acc[i][4], acc[i][5], acc[i][6], acc[i][7]);
    }
}

__global__ __launch_bounds__(256, 2) void gemm128_qkvg(const float* __restrict__ x,
    const float* __restrict__ Wq, const float* __restrict__ Wk,
    const float* __restrict__ Wv, const float* __restrict__ Wg)
{
    const float* Bw; float* C;
    switch (blockIdx.z) {
        case 0:  Bw = Wq; C = g_xq; break;
        case 1:  Bw = Wk; C = g_xk; break;
        case 2:  Bw = Wv; C = g_xv; break;
        default: Bw = Wg; C = g_g;  break;
    }
    gemm128_body(x, Bw, C, 0, 32);
}

// output projection: split-K x2 into partial buffers
__global__ __launch_bounds__(256, 2) void gemm_out_k(const float* __restrict__ Wo)
{
    float* C = blockIdx.z ? g_p1 : g_p0;
    gemm128_body(g_act, Wo, C, blockIdx.z * 256, 16);
}

__global__ __launch_bounds__(256) void add_out(float* __restrict__ out)
{
    int i = blockIdx.x * blockDim.x + threadIdx.x;
    if (i >= BT * KDIM / 4) return;
    float4 a = *(const float4*)(g_p0 + (size_t)i * 4);
    float4 b = *(const float4*)(g_p1 + (size_t)i * 4);
    *(float4*)(out + (size_t)i * 4) =
        make_float4(a.x + b.x, a.y + b.y, a.z + b.z, a.w + b.w);
}

// ---------------- beta / alpha small projection -------------------------------
__global__ __launch_bounds__(128) void small_proj(const float* __restrict__ x,
    const float* __restrict__ Wb, const float* __restrict__ bb,
    const float* __restrict__ Wgk, const float* __restrict__ bgk,
    const float* __restrict__ A_log, const float* __restrict__ dtb)
{
    __shared__ float xs[512];
    const int bt = blockIdx.x;
    const int tid = threadIdx.x;
    for (int i = tid; i < 512; i += 128) xs[i] = x[(size_t)bt * 512 + i];
    __syncthreads();
    const int warp = tid >> 5, lane = tid & 31;
#pragma unroll
    for (int oi = 0; oi < 4; oi++) {
        int out = warp * 4 + oi;
        const float* w = (out < 8) ? (Wb + out * 512) : (Wgk + (out - 8) * 512);
        float s = 0.0f;
#pragma unroll
        for (int i = 0; i < 16; i++) s = fmaf(xs[lane + i * 32], w[lane + i * 32], s);
        s = red32(s);
        if (lane == 0) {
            if (out < 8) {
                float z = s + bb[out];
                g_beta[bt * 8 + out] = 1.0f / (1.0f + expf(-z));
            } else {
                int h = out - 8;
                float z = s + bgk[h] + dtb[h];
                float sp = (z > 20.0f) ? z : log1pf(expf(z));
                g_alpha[bt * 8 + h] = expf(-expf(A_log[h]) * sp);
            }
        }
    }
}

// ---------------- depthwise causal conv (width 4) + silu ----------------------
__global__ __launch_bounds__(128) void conv_silu(
    const float* __restrict__ cqw, const float* __restrict__ cqb,
    const float* __restrict__ ckw, const float* __restrict__ ckb,
    const float* __restrict__ cvw, const float* __restrict__ cvb)
{
    const float *xin, *w, *bi; float* out;
    switch (blockIdx.y) {
        case 0:  xin = g_xq; w = cqw; bi = cqb; out = g_q; break;
        case 1:  xin = g_xk; w = ckw; bi = ckb; out = g_k; break;
        default: xin = g_xv; w = cvw; bi = cvb; out = g_v; break;
    }
    const int c = threadIdx.x * 4;
    const int t0 = blockIdx.x * 8;
    const int b  = blockIdx.z;

    float4 wr0 = *(const float4*)(w + (c + 0) * 4);
    float4 wr1 = *(const float4*)(w + (c + 1) * 4);
    float4 wr2 = *(const float4*)(w + (c + 2) * 4);
    float4 wr3 = *(const float4*)(w + (c + 3) * 4);
    float4 bias = *(const float4*)(bi + c);

    const float* xrow = xin + (size_t)b * TLEN * 512 + c;
    float*       orow = out + (size_t)b * TLEN * 512 + c;
    const float4 zero = make_float4(0.f, 0.f, 0.f, 0.f);

    float4 h0 = (t0 - 3 >= 0) ? *(const float4*)(xrow + (size_t)(t0 - 3) * 512) : zero;
    float4 h1 = (t0 - 2 >= 0) ? *(const float4*)(xrow + (size_t)(t0 - 2) * 512) : zero;
    float4 h2 = (t0 - 1 >= 0) ? *(const float4*)(xrow + (size_t)(t0 - 1) * 512) : zero;
    float4 cur = *(const float4*)(xrow + (size_t)t0 * 512);

#pragma unroll
    for (int t = t0; t < t0 + 8; t++) {
        float4 nxt = (t + 1 < TLEN) ? *(const float4*)(xrow + (size_t)(t + 1) * 512) : zero;
        float4 acc = bias;
        acc.x = fmaf(h0.x, wr0.x, acc.x); acc.x = fmaf(h1.x, wr0.y, acc.x);
        acc.x = fmaf(h2.x, wr0.z, acc.x); acc.x = fmaf(cur.x, wr0.w, acc.x);
        acc.y = fmaf(h0.y, wr1.x, acc.y); acc.y = fmaf(h1.y, wr1.y, acc.y);
        acc.y = fmaf(h2.y, wr1.z, acc.y); acc.y = fmaf(cur.y, wr1.w, acc.y);
        acc.z = fmaf(h0.z, wr2.x, acc.z); acc.z = fmaf(h1.z, wr2.y, acc.z);
        acc.z = fmaf(h2.z, wr2.z, acc.z); acc.z = fmaf(cur.z, wr2.w, acc.z);
        acc.w = fmaf(h0.w, wr3.x, acc.w); acc.w = fmaf(h1.w, wr3.y, acc.w);
        acc.w = fmaf(h2.w, wr3.z, acc.w); acc.w = fmaf(cur.w, wr3.w, acc.w);
        float4 o;
        o.x = acc.x / (1.0f + expf(-acc.x));
        o.y = acc.y / (1.0f + expf(-acc.y));
        o.z = acc.z / (1.0f + expf(-acc.z));
        o.w = acc.w / (1.0f + expf(-acc.w));
        *(float4*)(orow + (size_t)t * 512) = o;
        h0 = h1; h1 = h2; h2 = cur; cur = nxt;
    }
}

// ---------------- RoPE tables (fp64, recomputed every launch) -----------------
__global__ void rope_init()
{
    int idx = blockIdx.x * blockDim.x + threadIdx.x;
    if (idx >= TLEN * 32) return;
    int t = idx >> 5, j = idx & 31;
    const double PI = 3.14159265358979323846;
    double ar = (double)j / 32.0;
    double sbase = 10000.0 * pow(32.0, 64.0 / 62.0);
    double inv_freq = pow(sbase, -ar);
    double freq_extra = pow(10000.0, -ar);
    double wavelen = (2.0 * PI) / freq_extra;
    double ramp = (wavelen - 1.0) / 31.0;
    ramp = ramp < 0.0 ? 0.0 : (ramp > 1.0 ? 1.0 : ramp);
    double spf = 1.0 + 31.0 * ramp;
    double f = (double)t / spf * inv_freq;
    g_cos[idx] = (float)cos(f);
    g_sin[idx] = (float)sin(f);
}

// ---------------- RoPE + l2norm, in-place on g_q / g_k ------------------------
__global__ __launch_bounds__(256) void rope_l2norm()
{
    int gw = (blockIdx.x * blockDim.x + threadIdx.x) >> 5;
    int lane = threadIdx.x & 31;
    if (gw >= BT * NH) return;
    int t = (gw >> 3) & 1023;
    int j = (2 * lane) & 31;
    float c = g_cos[t * 32 + j], s = g_sin[t * 32 + j];
    size_t base = (size_t)gw * 64;
#pragma unroll
    for (int which = 0; which < 2; which++) {
        float* p = which ? g_k : g_q;
        float x1 = p[base + 2 * lane];
        float x2 = p[base + 2 * lane + 1];
        float o1 = x1 * c - x2 * s;
        float o2 = x1 * s + x2 * c;
        float ss = red32(o1 * o1 + o2 * o2);
        float inv = 1.0f / fmaxf(sqrtf(ss), 1e-12f);
        p[base + lane]      = o1 * inv;
        p[base + 32 + lane] = o2 * inv;
    }
}

// ---------------- c1[t]=k_t.k_{t-1}, c2[t]=k_t.k_{t-2} precompute -------------
__global__ __launch_bounds__(256) void c12_prep()
{
    int gw = (blockIdx.x * (blockDim.x >> 5)) + (threadIdx.x >> 5);
    int lane = threadIdx.x & 31;
    if (gw >= BT * NH) return;
    int h = gw & 7, bt = gw >> 3;
    int t = bt & 1023;
    const float* ka = g_k + (size_t)bt * 512 + h * 64;
    float2 xx = *(const float2*)(ka + lane * 2);
    float cv1 = 0.0f, cv2 = 0.0f;
    if (t > 0) {
        float2 yy = *(const float2*)(ka - 512 + lane * 2);
        cv1 = red32(fmaf(xx.x, yy.x, xx.y * yy.y));
    }
    if (t > 1) {
        float2 zz = *(const float2*)(ka - 1024 + lane * 2);
        cv2 = red32(fmaf(xx.x, zz.x, xx.y * zz.y));
    }
    if (lane == 0) {
        g_c1[(size_t)bt * 8 + h] = cv1;
        g_c2[(size_t)bt * 8 + h] = cv2;
    }
}

// ---------------- delta-rule scan (look-ahead-3, pipelined reductions) --------
// u_t = a_{t-1}a_{t-2} r_t + a_{t-1} w_{t-2} c2_t + w_{t-1} c1_t,
//   r_t = k_t^T S_{t-3}; w_t = b_t(v_t - a_t u_t); S_t = a_t S_{t-1} + w_t k_t.
__global__ __launch_bounds__(128) void scan_kernel()
{
    const int bh = blockIdx.x;
    const int eg = blockIdx.y;
    const int b = bh >> 3, h = bh & 7;
    const int w = threadIdx.x >> 5, lane = threadIdx.x & 31;
    const int el = lane >> 4, r = lane & 15;
    const int e  = eg * 8 + w * 2 + el;
    const int d0 = r * 4;

    const size_t head = ((size_t)b * TLEN * NH + h) * 64;
    const float* qp  = g_q + head + d0;
    const float* kp  = g_k + head + d0;
    const float* vpt = g_v + head + e;
    float*       op  = g_oc + head + e;
    const float* apt = g_alpha + (size_t)b * TLEN * NH + h;
    const float* bpt = g_beta  + (size_t)b * TLEN * NH + h;
    const float* cpt = g_c1    + (size_t)b * TLEN * NH + h;
    const float* c2pt= g_c2    + (size_t)b * TLEN * NH + h;

    float4 S = make_float4(0.f, 0.f, 0.f, 0.f);
    float w_prev1 = 0.f, w_prev2 = 0.f, a_prev1 = 0.f, a_prev2 = 0.f;
    float h1 = 0.f, oh1 = 0.f, r_use = 0.f, r_hold = 0.f;

    float4 kb[8];
    float4 qb[4];
    float  vb[4], ab[4], bb2[4], cb[4], c2b[4];
#pragma unroll
    for (int i = 0; i < 6; i++) kb[i] = *(const float4*)(kp + (size_t)i * 512);
    kb[6] = kb[7] = make_float4(0.f, 0.f, 0.f, 0.f);
#pragma unroll
    for (int i = 0; i < 4; i++) {
        qb[i]  = *(const float4*)(qp + (size_t)i * 512);
        vb[i]  = vpt[(size_t)i * 512];
        ab[i]  = apt[(size_t)i * 8];
        bb2[i] = bpt[(size_t)i * 8];
        cb[i]  = cpt[(size_t)i * 8];
        c2b[i] = c2pt[(size_t)i * 8];
    }

#pragma unroll 8
    for (int t = 0; t < TLEN; t++) {
        const float4 kc  = kb[t & 7];
        const float4 kf  = kb[(t + 3) & 7];   // k_{t+3} for r partial
        const float4 qc  = qb[t & 3];
        const float  vc  = vb[t & 3];
        const float  ac  = ab[t & 3];
        const float  bc  = bb2[t & 3];
        const float  c1c = cb[t & 3];
        const float  c2c = c2b[t & 3];

        float u = fmaf(a_prev1 * a_prev2, r_use,
                       fmaf(a_prev1 * w_prev2, c2c, w_prev1 * c1c));
        float wv = bc * fmaf(-ac, u, vc);
        S.x = fmaf(kc.x, wv, ac * S.x);
        S.y = fmaf(kc.y, wv, ac * S.y);
        S.z = fmaf(kc.z, wv, ac * S.z);
        S.w = fmaf(kc.w, wv, ac * S.w);

        float h2 = h1 + __shfl_xor_sync(0xffffffffu, h1, 2);
        float rnew = h2 + __shfl_xor_sync(0xffffffffu, h2, 1);
        float og = oh1 + __shfl_xor_sync(0xffffffffu, oh1, 2);
        float o_fin = og + __shfl_xor_sync(0xffffffffu, og, 1);
        if (r == 0 && t > 0) op[-512] = o_fin;

        float rp = fmaf(kf.x, S.x, fmaf(kf.y, S.y, fmaf(kf.z, S.z, kf.w * S.w)));
        float rh = rp + __shfl_xor_sync(0xffffffffu, rp, 8);
        h1 = rh + __shfl_xor_sync(0xffffffffu, rh, 4);
        float opp = fmaf(qc.x, S.x, fmaf(qc.y, S.y, fmaf(qc.z, S.z, qc.w * S.w)));
        float oh = opp + __shfl_xor_sync(0xffffffffu, opp, 8);
        oh1 = oh + __shfl_xor_sync(0xffffffffu, oh, 4);

        r_use = r_hold; r_hold = rnew;
        w_prev2 = w_prev1; w_prev1 = wv;
        a_prev2 = a_prev1; a_prev1 = ac;

        kb[(t + 6) & 7] = *(const float4*)(kp + 6 * 512);
        qb[(t + 4) & 3] = *(const float4*)(qp + 4 * 512);
        vb[(t + 4) & 3]  = vpt[4 * 512];
        ab[(t + 4) & 3]  = apt[4 * 8];
        bb2[(t + 4) & 3] = bpt[4 * 8];
        cb[(t + 4) & 3]  = cpt[4 * 8];
        c2b[(t + 4) & 3] = c2pt[4 * 8];
        kp += 512; qp += 512; vpt += 512; op += 512;
        apt += 8; bpt += 8; cpt += 8; c2pt += 8;
    }
    float og = oh1 + __shfl_xor_sync(0xffffffffu, oh1, 2);
    float o_fin = og + __shfl_xor_sync(0xffffffffu, og, 1);
    if (r == 0) op[-512] = o_fin;
}

// ---------------- post: +D*v, RMS norm, gate ----------------------------------
__global__ __launch_bounds__(256) void postproc(const float* __restrict__ D,
                                                const float* __restrict__ onw)
{
    int gw = (blockIdx.x * blockDim.x + threadIdx.x) >> 5;
    int lane = threadIdx.x & 31;
    if (gw >= BT * NH) return;
    int h = gw & 7;
    size_t base = (size_t)gw * 64;
    float d = D[h];
    float o1 = g_oc[base + lane]      + d * g_v[base + lane];
    float o2 = g_oc[base + 32 + lane] + d * g_v[base + 32 + lane];
    float ss = red32(o1 * o1 + o2 * o2);
    float sc = rsqrtf(ss * (1.0f / 64.0f) + 1e-6f);
    float on1 = o1 * sc * onw[lane];
    float on2 = o2 * sc * onw[32 + lane];
    float g1 = g_g[base + lane], g2 = g_g[base + 32 + lane];
    g_act[base + lane]      = g1 * (on1 / (1.0f + expf(-on1)));
    g_act[base + 32 + lane] = g2 * (on2 / (1.0f + expf(-on2)));
}

// ---------------- launch ------------------------------------------------------
extern "C" void kernel_launch(void* const* d_in, const int* in_sizes, int n_in,
                              void* d_out, int out_size)
{
    const float* x    = (const float*)d_in[0];
    const float* Wq   = (const float*)d_in[1];
    const float* Wk   = (const float*)d_in[2];
    const float* Wv   = (const float*)d_in[3];
    const float* Wg   = (const float*)d_in[4];
    const float* Wo   = (const float*)d_in[5];
    const float* Wb   = (const float*)d_in[6];
    const float* bb   = (const float*)d_in[7];
    const float* Wgk  = (const float*)d_in[8];
    const float* bgk  = (const float*)d_in[9];
    const float* cqw  = (const float*)d_in[10];
    const float* cqb  = (const float*)d_in[11];
    const float* ckw  = (const float*)d_in[12];
    const float* ckb  = (const float*)d_in[13];
    const float* cvw  = (const float*)d_in[14];
    const float* cvb  = (const float*)d_in[15];
    const float* A_log= (const float*)d_in[16];
    const float* D    = (const float*)d_in[17];
    const float* dtb  = (const float*)d_in[18];
    const float* onw  = (const float*)d_in[19];
    float* out = (float*)d_out;

    rope_init<<<(TLEN * 32 + 255) / 256, 256>>>();
    gemm128_qkvg<<<dim3(4, 16, 4), 256>>>(x, Wq, Wk, Wv, Wg);
    small_proj<<<BT, 128>>>(x, Wb, bb, Wgk, bgk, A_log, dtb);
    conv_silu<<<dim3(TLEN / 8, 3, 2), 128>>>(cqw, cqb, ckw, ckb, cvw, cvb);
    rope_l2norm<<<2048, 256>>>();
    c12_prep<<<(BT * NH + 7) / 8, 256>>>();
    scan_kernel<<<dim3(16, 8), 128>>>();
    postproc<<<2048, 256>>>(D, onw);
    gemm_out_k<<<dim3(4, 16, 2), 256>>>(Wo);
    add_out<<<(BT * KDIM / 4 + 255) / 256, 256>>>(out);
}

// round 17
// speedup vs baseline: 1.3274x; 1.0388x over previous
#include <cuda_runtime.h>
#include <cstdint>
#include <math.h>

#define BATCH 2
#define TLEN  1024
#define NH    8
#define HDIM  64
#define HID   512
#define KDIM  512
#define BT    (BATCH*TLEN)
#define PADROWS 8

// ---------------- scratch (q/k/v + gating padded for unconditional prefetch) --
__device__ float g_xq[BT*KDIM];
__device__ float g_xk[BT*KDIM];
__device__ float g_xv[BT*KDIM];
__device__ float g_q [BT*KDIM + PADROWS*KDIM];
__device__ float g_k [BT*KDIM + PADROWS*KDIM];
__device__ float g_v [BT*KDIM + PADROWS*KDIM];
__device__ float g_g [BT*KDIM];
__device__ float g_oc[BT*KDIM];
__device__ float g_act[BT*KDIM];
__device__ float g_p0[BT*KDIM];
__device__ float g_p1[BT*KDIM];
__device__ float g_beta [BT*NH + PADROWS*NH];
__device__ float g_alpha[BT*NH + PADROWS*NH];
__device__ float g_c1   [BT*NH + PADROWS*NH];
__device__ float g_c2   [BT*NH + PADROWS*NH];
__device__ float g_cos[TLEN*32];
__device__ float g_sin[TLEN*32];

// ---------------- helpers ----------------
__device__ __forceinline__ float red32(float x)
{
#pragma unroll
    for (int m = 16; m; m >>= 1) x += __shfl_xor_sync(0xffffffffu, x, m);
    return x;
}

// ---------------- GEMM 128x128 body, parametric K range -----------------------
__device__ __forceinline__ void gemm128_body(const float* __restrict__ A,
                                             const float* __restrict__ Bw,
                                             float* __restrict__ C,
                                             int kbase, int KT)
{
    __shared__ __align__(16) float As[2][16][132];
    __shared__ __align__(16) float Bs[2][16][132];
    const int tid = threadIdx.x;
    const int tx = tid & 15, ty = tid >> 4;
    const int m0 = blockIdx.y * 128, n0 = blockIdx.x * 128;

    const int r0 = (tid)       >> 2, q0 = ((tid)       & 3) << 2;
    const int r1 = (tid + 256) >> 2, q1 = ((tid + 256) & 3) << 2;

    const float* aptr0 = A  + (size_t)(m0 + r0) * 512 + kbase + q0;
    const float* aptr1 = A  + (size_t)(m0 + r1) * 512 + kbase + q1;
    const float* bptr0 = Bw + (size_t)(n0 + r0) * 512 + kbase + q0;
    const float* bptr1 = Bw + (size_t)(n0 + r1) * 512 + kbase + q1;

    float acc[8][8];
#pragma unroll
    for (int i = 0; i < 8; i++)
#pragma unroll
        for (int j = 0; j < 8; j++) acc[i][j] = 0.0f;

    float4 va0 = *(const float4*)(aptr0);
    float4 va1 = *(const float4*)(aptr1);
    float4 vb0 = *(const float4*)(bptr0);
    float4 vb1 = *(const float4*)(bptr1);
    {
        As[0][q0 + 0][r0] = va0.x; As[0][q0 + 1][r0] = va0.y;
        As[0][q0 + 2][r0] = va0.z; As[0][q0 + 3][r0] = va0.w;
        As[0][q1 + 0][r1] = va1.x; As[0][q1 + 1][r1] = va1.y;
        As[0][q1 + 2][r1] = va1.z; As[0][q1 + 3][r1] = va1.w;
        Bs[0][q0 + 0][r0] = vb0.x; Bs[0][q0 + 1][r0] = vb0.y;
        Bs[0][q0 + 2][r0] = vb0.z; Bs[0][q0 + 3][r0] = vb0.w;
        Bs[0][q1 + 0][r1] = vb1.x; Bs[0][q1 + 1][r1] = vb1.y;
        Bs[0][q1 + 2][r1] = vb1.z; Bs[0][q1 + 3][r1] = vb1.w;
    }
    __syncthreads();

    for (int kt = 0; kt < KT; kt++) {
        const int cur = kt & 1;
        if (kt + 1 < KT) {
            int ko = (kt + 1) * 16;
            va0 = *(const float4*)(aptr0 + ko);
            va1 = *(const float4*)(aptr1 + ko);
            vb0 = *(const float4*)(bptr0 + ko);
            vb1 = *(const float4*)(bptr1 + ko);
        }
#pragma unroll
        for (int kk = 0; kk < 16; kk++) {
            float4 a0 = *(const float4*)&As[cur][kk][ty * 8];
            float4 a1 = *(const float4*)&As[cur][kk][ty * 8 + 4];
            float4 b0 = *(const float4*)&Bs[cur][kk][tx * 8];
            float4 b1 = *(const float4*)&Bs[cur][kk][tx * 8 + 4];
            float av[8] = {a0.x, a0.y, a0.z, a0.w, a1.x, a1.y, a1.z, a1.w};
            float bv[8] = {b0.x, b0.y, b0.z, b0.w, b1.x, b1.y, b1.z, b1.w};
#pragma unroll
            for (int i = 0; i < 8; i++)
#pragma unroll
                for (int j = 0; j < 8; j++)
                    acc[i][j] = fmaf(av[i], bv[j], acc[i][j]);
        }
        if (kt + 1 < KT) {
            const int nxt = cur ^ 1;
            As[nxt][q0 + 0][r0] = va0.x; As[nxt][q0 + 1][r0] = va0.y;
            As[nxt][q0 + 2][r0] = va0.z; As[nxt][q0 + 3][r0] = va0.w;
            As[nxt][q1 + 0][r1] = va1.x; As[nxt][q1 + 1][r1] = va1.y;
            As[nxt][q1 + 2][r1] = va1.z; As[nxt][q1 + 3][r1] = va1.w;
            Bs[nxt][q0 + 0][r0] = vb0.x; Bs[nxt][q0 + 1][r0] = vb0.y;
            Bs[nxt][q0 + 2][r0] = vb0.z; Bs[nxt][q0 + 3][r0] = vb0.w;
            Bs[nxt][q1 + 0][r1] = vb1.x; Bs[nxt][q1 + 1][r1] = vb1.y;
            Bs[nxt][q1 + 2][r1] = vb1.z; Bs[nxt][q1 + 3][r1] = vb1.w;
            __syncthreads();
        }
    }
#pragma unroll
    for (int i = 0; i < 8; i++) {
        float* crow = C + (size_t)(m0 + ty * 8 + i) * 512 + n0 + tx * 8;
        *(float4*)(crow)     = make_float4(acc[i][0], acc[i][1], acc[i][2], acc[i][3]);
        *(float4*)(crow + 4) = make_float4(acc[i][4], acc[i][5], acc[i][6], acc[i][7]);
    }
}

__global__ __launch_bounds__(256, 2) void gemm128_qkvg(const float* __restrict__ x,
    const float* __restrict__ Wq, const float* __restrict__ Wk,
    const float* __restrict__ Wv, const float* __restrict__ Wg)
{
    const float* Bw; float* C;
    switch (blockIdx.z) {
        case 0:  Bw = Wq; C = g_xq; break;
        case 1:  Bw = Wk; C = g_xk; break;
        case 2:  Bw = Wv; C = g_xv; break;
        default: Bw = Wg; C = g_g;  break;
    }
    gemm128_body(x, Bw, C, 0, 32);
}

// output projection: split-K x2 into partial buffers
__global__ __launch_bounds__(256, 2) void gemm_out_k(const float* __restrict__ Wo)
{
    float* C = blockIdx.z ? g_p1 : g_p0;
    gemm128_body(g_act, Wo, C, blockIdx.z * 256, 16);
}

__global__ __launch_bounds__(256) void add_out(float* __restrict__ out)
{
    int i = blockIdx.x * blockDim.x + threadIdx.x;
    if (i >= BT * KDIM / 4) return;
    float4 a = *(const float4*)(g_p0 + (size_t)i * 4);
    float4 b = *(const float4*)(g_p1 + (size_t)i * 4);
    *(float4*)(out + (size_t)i * 4) =
        make_float4(a.x + b.x, a.y + b.y, a.z + b.z, a.w + b.w);
}

// ---------------- beta / alpha small projection -------------------------------
__global__ __launch_bounds__(128) void small_proj(const float* __restrict__ x,
    const float* __restrict__ Wb, const float* __restrict__ bb,
    const float* __restrict__ Wgk, const float* __restrict__ bgk,
    const float* __restrict__ A_log, const float* __restrict__ dtb)
{
    __shared__ float xs[512];
    const int bt = blockIdx.x;
    const int tid = threadIdx.x;
    for (int i = tid; i < 512; i += 128) xs[i] = x[(size_t)bt * 512 + i];
    __syncthreads();
    const int warp = tid >> 5, lane = tid & 31;
#pragma unroll
    for (int oi = 0; oi < 4; oi++) {
        int out = warp * 4 + oi;
        const float* w = (out < 8) ? (Wb + out * 512) : (Wgk + (out - 8) * 512);
        float s = 0.0f;
#pragma unroll
        for (int i = 0; i < 16; i++) s = fmaf(xs[lane + i * 32], w[lane + i * 32], s);
        s = red32(s);
        if (lane == 0) {
            if (out < 8) {
                float z = s + bb[out];
                g_beta[bt * 8 + out] = 1.0f / (1.0f + expf(-z));
            } else {
                int h = out - 8;
                float z = s + bgk[h] + dtb[h];
                float sp = (z > 20.0f) ? z : log1pf(expf(z));
                g_alpha[bt * 8 + h] = expf(-expf(A_log[h]) * sp);
            }
        }
    }
}

// ---------------- depthwise causal conv (width 4) + silu ----------------------
__global__ __launch_bounds__(128) void conv_silu(
    const float* __restrict__ cqw, const float* __restrict__ cqb,
    const float* __restrict__ ckw, const float* __restrict__ ckb,
    const float* __restrict__ cvw, const float* __restrict__ cvb)
{
    const float *xin, *w, *bi; float* out;
    switch (blockIdx.y) {
        case 0:  xin = g_xq; w = cqw; bi = cqb; out = g_q; break;
        case 1:  xin = g_xk; w = ckw; bi = ckb; out = g_k; break;
        default: xin = g_xv; w = cvw; bi = cvb; out = g_v; break;
    }
    const int c = threadIdx.x * 4;
    const int t0 = blockIdx.x * 4;
    const int b  = blockIdx.z;

    float4 wr0 = *(const float4*)(w + (c + 0) * 4);
    float4 wr1 = *(const float4*)(w + (c + 1) * 4);
    float4 wr2 = *(const float4*)(w + (c + 2) * 4);
    float4 wr3 = *(const float4*)(w + (c + 3) * 4);
    float4 bias = *(const float4*)(bi + c);

    const float* xrow = xin + (size_t)b * TLEN * 512 + c;
    float*       orow = out + (size_t)b * TLEN * 512 + c;
    const float4 zero = make_float4(0.f, 0.f, 0.f, 0.f);

    float4 h0 = (t0 - 3 >= 0) ? *(const float4*)(xrow + (size_t)(t0 - 3) * 512) : zero;
    float4 h1 = (t0 - 2 >= 0) ? *(const float4*)(xrow + (size_t)(t0 - 2) * 512) : zero;
    float4 h2 = (t0 - 1 >= 0) ? *(const float4*)(xrow + (size_t)(t0 - 1) * 512) : zero;
    float4 cur = *(const float4*)(xrow + (size_t)t0 * 512);

#pragma unroll
    for (int t = t0; t < t0 + 4; t++) {
        float4 nxt = (t + 1 < TLEN) ? *(const float4*)(xrow + (size_t)(t + 1) * 512) : zero;
        float4 acc = bias;
        acc.x = fmaf(h0.x, wr0.x, acc.x); acc.x = fmaf(h1.x, wr0.y, acc.x);
        acc.x = fmaf(h2.x, wr0.z, acc.x); acc.x = fmaf(cur.x, wr0.w, acc.x);
        acc.y = fmaf(h0.y, wr1.x, acc.y); acc.y = fmaf(h1.y, wr1.y, acc.y);
        acc.y = fmaf(h2.y, wr1.z, acc.y); acc.y = fmaf(cur.y, wr1.w, acc.y);
        acc.z = fmaf(h0.z, wr2.x, acc.z); acc.z = fmaf(h1.z, wr2.y, acc.z);
        acc.z = fmaf(h2.z, wr2.z, acc.z); acc.z = fmaf(cur.z, wr2.w, acc.z);
        acc.w = fmaf(h0.w, wr3.x, acc.w); acc.w = fmaf(h1.w, wr3.y, acc.w);
        acc.w = fmaf(h2.w, wr3.z, acc.w); acc.w = fmaf(cur.w, wr3.w, acc.w);
        float4 o;
        o.x = acc.x / (1.0f + expf(-acc.x));
        o.y = acc.y / (1.0f + expf(-acc.y));
        o.z = acc.z / (1.0f + expf(-acc.z));
        o.w = acc.w / (1.0f + expf(-acc.w));
        *(float4*)(orow + (size_t)t * 512) = o;
        h0 = h1; h1 = h2; h2 = cur; cur = nxt;
    }
}

// ---------------- RoPE tables (fp64, recomputed every launch) -----------------
__global__ void rope_init()
{
    int idx = blockIdx.x * blockDim.x + threadIdx.x;
    if (idx >= TLEN * 32) return;
    int t = idx >> 5, j = idx & 31;
    const double PI = 3.14159265358979323846;
    double ar = (double)j / 32.0;
    double sbase = 10000.0 * pow(32.0, 64.0 / 62.0);
    double inv_freq = pow(sbase, -ar);
    double freq_extra = pow(10000.0, -ar);
    double wavelen = (2.0 * PI) / freq_extra;
    double ramp = (wavelen - 1.0) / 31.0;
    ramp = ramp < 0.0 ? 0.0 : (ramp > 1.0 ? 1.0 : ramp);
    double spf = 1.0 + 31.0 * ramp;
    double f = (double)t / spf * inv_freq;
    g_cos[idx] = (float)cos(f);
    g_sin[idx] = (float)sin(f);
}

// ---------------- RoPE + l2norm, in-place on g_q / g_k ------------------------
__global__ __launch_bounds__(256) void rope_l2norm()
{
    int gw = (blockIdx.x * blockDim.x + threadIdx.x) >> 5;
    int lane = threadIdx.x & 31;
    if (gw >= BT * NH) return;
    int t = (gw >> 3) & 1023;
    int j = (2 * lane) & 31;
    float c = g_cos[t * 32 + j], s = g_sin[t * 32 + j];
    size_t base = (size_t)gw * 64;
#pragma unroll
    for (int which = 0; which < 2; which++) {
        float* p = which ? g_k : g_q;
        float x1 = p[base + 2 * lane];
        float x2 = p[base + 2 * lane + 1];
        float o1 = x1 * c - x2 * s;
        float o2 = x1 * s + x2 * c;
        float ss = red32(o1 * o1 + o2 * o2);
        float inv = 1.0f / fmaxf(sqrtf(ss), 1e-12f);
        p[base + lane]      = o1 * inv;
        p[base + 32 + lane] = o2 * inv;
    }
}

// ---------------- c1[t]=k_t.k_{t-1}, c2[t]=k_t.k_{t-2} precompute -------------
__global__ __launch_bounds__(256) void c12_prep()
{
    int gw = (blockIdx.x * (blockDim.x >> 5)) + (threadIdx.x >> 5);
    int lane = threadIdx.x & 31;
    if (gw >= BT * NH) return;
    int h = gw & 7, bt = gw >> 3;
    int t = bt & 1023;
    const float* ka = g_k + (size_t)bt * 512 + h * 64;
    float2 xx = *(const float2*)(ka + lane * 2);
    float cv1 = 0.0f, cv2 = 0.0f;
    if (t > 0) {
        float2 yy = *(const float2*)(ka - 512 + lane * 2);
        cv1 = red32(fmaf(xx.x, yy.x, xx.y * yy.y));
    }
    if (t > 1) {
        float2 zz = *(const float2*)(ka - 1024 + lane * 2);
        cv2 = red32(fmaf(xx.x, zz.x, xx.y * zz.y));
    }
    if (lane == 0) {
        g_c1[(size_t)bt * 8 + h] = cv1;
        g_c2[(size_t)bt * 8 + h] = cv2;
    }
}

// ---------------- delta-rule scan (look-ahead-3, pipelined reductions) --------
// u_t = a_{t-1}a_{t-2} r_t + a_{t-1} w_{t-2} c2_t + w_{t-1} c1_t,
//   r_t = k_t^T S_{t-3}; w_t = b_t(v_t - a_t u_t); S_t = a_t S_{t-1} + w_t k_t.
__global__ __launch_bounds__(128) void scan_kernel()
{
    const int bh = blockIdx.x;
    const int eg = blockIdx.y;
    const int b = bh >> 3, h = bh & 7;
    const int w = threadIdx.x >> 5, lane = threadIdx.x & 31;
    const int el = lane >> 4, r = lane & 15;
    const int e  = eg * 8 + w * 2 + el;
    const int d0 = r * 4;

    const size_t head = ((size_t)b * TLEN * NH + h) * 64;
    const float* qp  = g_q + head + d0;
    const float* kp  = g_k + head + d0;
    const float* vpt = g_v + head + e;
    float*       op  = g_oc + head + e;
    const float* apt = g_alpha + (size_t)b * TLEN * NH + h;
    const float* bpt = g_beta  + (size_t)b * TLEN * NH + h;
    const float* cpt = g_c1    + (size_t)b * TLEN * NH + h;
    const float* c2pt= g_c2    + (size_t)b * TLEN * NH + h;

    float4 S = make_float4(0.f, 0.f, 0.f, 0.f);
    float w_prev1 = 0.f, w_prev2 = 0.f, a_prev1 = 0.f, a_prev2 = 0.f;
    float h1 = 0.f, oh1 = 0.f, r_use = 0.f, r_hold = 0.f;

    float4 kb[8];
    float4 qb[4];
    float  vb[4], ab[4], bb2[4], cb[4], c2b[4];
#pragma unroll
    for (int i = 0; i < 6; i++) kb[i] = *(const float4*)(kp + (size_t)i * 512);
    kb[6] = kb[7] = make_float4(0.f, 0.f, 0.f, 0.f);
#pragma unroll
    for (int i = 0; i < 4; i++) {
        qb[i]  = *(const float4*)(qp + (size_t)i * 512);
        vb[i]  = vpt[(size_t)i * 512];
        ab[i]  = apt[(size_t)i * 8];
        bb2[i] = bpt[(size_t)i * 8];
        cb[i]  = cpt[(size_t)i * 8];
        c2b[i] = c2pt[(size_t)i * 8];
    }

#pragma unroll 8
    for (int t = 0; t < TLEN; t++) {
        const float4 kc  = kb[t & 7];
        const float4 kf  = kb[(t + 3) & 7];   // k_{t+3} for r partial
        const float4 qc  = qb[t & 3];
        const float  vc  = vb[t & 3];
        const float  ac  = ab[t & 3];
        const float  bc  = bb2[t & 3];
        const float  c1c = cb[t & 3];
        const float  c2c = c2b[t & 3];

        float u = fmaf(a_prev1 * a_prev2, r_use,
                       fmaf(a_prev1 * w_prev2, c2c, w_prev1 * c1c));
        float wv = bc * fmaf(-ac, u, vc);
        S.x = fmaf(kc.x, wv, ac * S.x);
        S.y = fmaf(kc.y, wv, ac * S.y);
        S.z = fmaf(kc.z, wv, ac * S.z);
        S.w = fmaf(kc.w, wv, ac * S.w);

        float h2 = h1 + __shfl_xor_sync(0xffffffffu, h1, 2);
        float rnew = h2 + __shfl_xor_sync(0xffffffffu, h2, 1);
        float og = oh1 + __shfl_xor_sync(0xffffffffu, oh1, 2);
        float o_fin = og + __shfl_xor_sync(0xffffffffu, og, 1);
        if (r == 0 && t > 0) op[-512] = o_fin;

        float rp = fmaf(kf.x, S.x, fmaf(kf.y, S.y, fmaf(kf.z, S.z, kf.w * S.w)));
        float rh = rp + __shfl_xor_sync(0xffffffffu, rp, 8);
        h1 = rh + __shfl_xor_sync(0xffffffffu, rh, 4);
        float opp = fmaf(qc.x, S.x, fmaf(qc.y, S.y, fmaf(qc.z, S.z, qc.w * S.w)));
        float oh = opp + __shfl_xor_sync(0xffffffffu, opp, 8);
        oh1 = oh + __shfl_xor_sync(0xffffffffu, oh, 4);

        r_use = r_hold; r_hold = rnew;
        w_prev2 = w_prev1; w_prev1 = wv;
        a_prev2 = a_prev1; a_prev1 = ac;

        kb[(t + 6) & 7] = *(const float4*)(kp + 6 * 512);
        qb[(t + 4) & 3] = *(const float4*)(qp + 4 * 512);
        vb[(t + 4) & 3]  = vpt[4 * 512];
        ab[(t + 4) & 3]  = apt[4 * 8];
        bb2[(t + 4) & 3] = bpt[4 * 8];
        cb[(t + 4) & 3]  = cpt[4 * 8];
        c2b[(t + 4) & 3] = c2pt[4 * 8];
        kp += 512; qp += 512; vpt += 512; op += 512;
        apt += 8; bpt += 8; cpt += 8; c2pt += 8;
    }
    float og = oh1 + __shfl_xor_sync(0xffffffffu, oh1, 2);
    float o_fin = og + __shfl_xor_sync(0xffffffffu, og, 1);
    if (r == 0) op[-512] = o_fin;
}

// ---------------- post: +D*v, RMS norm, gate ----------------------------------
__global__ __launch_bounds__(256) void postproc(const float* __restrict__ D,
                                                const float* __restrict__ onw)
{
    int gw = (blockIdx.x * blockDim.x + threadIdx.x) >> 5;
    int lane = threadIdx.x & 31;
    if (gw >= BT * NH) return;
    int h = gw & 7;
    size_t base = (size_t)gw * 64;
    float d = D[h];
    float o1 = g_oc[base + lane]      + d * g_v[base + lane];
    float o2 = g_oc[base + 32 + lane] + d * g_v[base + 32 + lane];
    float ss = red32(o1 * o1 + o2 * o2);
    float sc = rsqrtf(ss * (1.0f / 64.0f) + 1e-6f);
    float on1 = o1 * sc * onw[lane];
    float on2 = o2 * sc * onw[32 + lane];
    float g1 = g_g[base + lane], g2 = g_g[base + 32 + lane];
    g_act[base + lane]      = g1 * (on1 / (1.0f + expf(-on1)));
    g_act[base + 32 + lane] = g2 * (on2 / (1.0f + expf(-on2)));
}

// ---------------- launch ------------------------------------------------------
extern "C" void kernel_launch(void* const* d_in, const int* in_sizes, int n_in,
                              void* d_out, int out_size)
{
    const float* x    = (const float*)d_in[0];
    const float* Wq   = (const float*)d_in[1];
    const float* Wk   = (const float*)d_in[2];
    const float* Wv   = (const float*)d_in[3];
    const float* Wg   = (const float*)d_in[4];
    const float* Wo   = (const float*)d_in[5];
    const float* Wb   = (const float*)d_in[6];
    const float* bb   = (const float*)d_in[7];
    const float* Wgk  = (const float*)d_in[8];
    const float* bgk  = (const float*)d_in[9];
    const float* cqw  = (const float*)d_in[10];
    const float* cqb  = (const float*)d_in[11];
    const float* ckw  = (const float*)d_in[12];
    const float* ckb  = (const float*)d_in[13];
    const float* cvw  = (const float*)d_in[14];
    const float* cvb  = (const float*)d_in[15];
    const float* A_log= (const float*)d_in[16];
    const float* D    = (const float*)d_in[17];
    const float* dtb  = (const float*)d_in[18];
    const float* onw  = (const float*)d_in[19];
    float* out = (float*)d_out;

    rope_init<<<(TLEN * 32 + 255) / 256, 256>>>();
    gemm128_qkvg<<<dim3(4, 16, 4), 256>>>(x, Wq, Wk, Wv, Wg);
    small_proj<<<BT, 128>>>(x, Wb, bb, Wgk, bgk, A_log, dtb);
    conv_silu<<<dim3(TLEN / 4, 3, 2), 128>>>(cqw, cqb, ckw, ckb, cvw, cvb);
    rope_l2norm<<<2048, 256>>>();
    c12_prep<<<(BT * NH + 7) / 8, 256>>>();
    scan_kernel<<<dim3(16, 8), 128>>>();
    postproc<<<2048, 256>>>(D, onw);
    gemm_out_k<<<dim3(4, 16, 2), 256>>>(Wo);
    add_out<<<(BT * KDIM / 4 + 255) / 256, 256>>>(out);
}